// round 10
// baseline (speedup 1.0000x reference)
#include <cuda_runtime.h>
#include <cuda_fp16.h>
#include <math.h>

#define LTOT 4096
#define CCH  96
#define DCH  96
#define KDIR 6
#define NST  16
#define RRK  6

__device__ __forceinline__ float2 ex2_pair(float a, float b) {
    __half2 h = __floats2half2_rn(a, b);
    unsigned hr;
    asm("ex2.approx.f16x2 %0, %1;" : "=r"(hr) : "r"(*(unsigned*)&h));
    return __half22float2(*(__half2*)&hr);
}

// ---------------- scratch (device globals; no allocation allowed) ----------------
__device__ float g_wint[CCH * 192];          // in_proj_w transposed [c][e]
__device__ float g_wpad[3 * DCH * 80];       // x_proj_w fused pairs, padded [k'][d][80]
__device__ float g_A2[KDIR * DCH * NST];     // -exp(A_log) * log2(e)
__device__ float g_wot[DCH * CCH];           // out_proj_w transposed [e][c]
__device__ float g_xh[DCH * LTOT];           // conv input  [ch][s]
__device__ float g_z[LTOT * CCH];            // gate        [s][e]
__device__ float g_xs[3 * DCH * LTOT];       // scan inputs [k'][d][l]
__device__ float g_dtr[KDIR * LTOT * RRK];   // raw dt      [k][l][r]
__device__ float g_Bm[KDIR * LTOT * NST];    // B           [k][l][n]
__device__ float g_Cm[KDIR * LTOT * NST];    // C           [k][l][n]
__device__ float2 g_dx[KDIR * LTOT * DCH];   // (softplus dt, flip-applied xs) [k][l][d]
__device__ float g_ys[KDIR * LTOT * DCH];    // scan output [k][l][d]

// ---------------- prep: weight transposes + A2 = -exp(A_log)*log2e ----------------
__global__ void k0_prep(const float* __restrict__ in_proj_w,
                        const float* __restrict__ x_proj_w,
                        const float* __restrict__ A_log,
                        const float* __restrict__ out_proj_w) {
    int i = blockIdx.x * blockDim.x + threadIdx.x;
    if (i < CCH * 192) {                       // g_wint[c][e] = in_proj_w[e][c]
        int c = i / 192, e = i % 192;
        g_wint[i] = in_proj_w[e * CCH + c];
    }
    if (i < 3 * DCH * 80) {                    // fused+padded weights [kp][d][80]
        int kp = i / (DCH * 80);
        int rem = i % (DCH * 80);
        int d = rem / 80, c = rem % 80;
        float v = 0.0f;
        if (c < 76) {
            int kk = (c < 38) ? kp : kp + 3;
            int cc = (c < 38) ? c : c - 38;
            v = x_proj_w[(kk * 38 + cc) * DCH + d];
        }
        g_wpad[i] = v;
    }
    if (i < KDIR * DCH * NST) g_A2[i] = -expf(A_log[i]) * 1.4426950408889634f;
    if (i < DCH * CCH) {                       // g_wot[e][c] = out_proj_w[c][e]
        int e = i / CCH, c = i % CCH;
        g_wot[i] = out_proj_w[c * DCH + e];
    }
}

// ---------------- k1 v2: LayerNorm(C=96) + in_proj (96 -> 192), 32-l tiles ----------------
__global__ __launch_bounds__(192) void k1_ln_inproj(const float* __restrict__ x,
                                                    const float* __restrict__ lw,
                                                    const float* __restrict__ lb) {
    __shared__ float sxn[32][96];
    int l0 = blockIdx.x * 32;
    int t = threadIdx.x, w = t >> 5, lane = t & 31;

    for (int r = w; r < 32; r += 6) {
        const float* xr = x + (size_t)(l0 + r) * CCH;
        float v0 = xr[lane], v1 = xr[lane + 32], v2 = xr[lane + 64];
        float s = v0 + v1 + v2;
        float sq = v0 * v0 + v1 * v1 + v2 * v2;
        #pragma unroll
        for (int o = 16; o; o >>= 1) {
            s += __shfl_xor_sync(0xFFFFFFFFu, s, o);
            sq += __shfl_xor_sync(0xFFFFFFFFu, sq, o);
        }
        float m = s * (1.0f / 96.0f);
        float var = fmaf(-m, m, sq * (1.0f / 96.0f));
        float inv = rsqrtf(var + 1e-6f);
        sxn[r][lane]      = fmaf((v0 - m) * inv, lw[lane],      lb[lane]);
        sxn[r][lane + 32] = fmaf((v1 - m) * inv, lw[lane + 32], lb[lane + 32]);
        sxn[r][lane + 64] = fmaf((v2 - m) * inv, lw[lane + 64], lb[lane + 64]);
    }
    __syncthreads();

    float acc[32];
    #pragma unroll
    for (int r = 0; r < 32; r++) acc[r] = 0.0f;
    for (int j = 0; j < 96; j += 4) {
        float w0 = g_wint[(j + 0) * 192 + t];
        float w1 = g_wint[(j + 1) * 192 + t];
        float w2 = g_wint[(j + 2) * 192 + t];
        float w3 = g_wint[(j + 3) * 192 + t];
        #pragma unroll
        for (int r = 0; r < 32; r++) {
            float4 xv = *(const float4*)&sxn[r][j];
            acc[r] = fmaf(w0, xv.x, fmaf(w1, xv.y, fmaf(w2, xv.z, fmaf(w3, xv.w, acc[r]))));
        }
    }
    if (t < 96) {
        float* o = g_xh + (size_t)t * LTOT + l0;
        #pragma unroll
        for (int r = 0; r < 32; r += 4)
            *(float4*)&o[r] = make_float4(acc[r], acc[r + 1], acc[r + 2], acc[r + 3]);
    } else {
        int e = t - 96;
        #pragma unroll
        for (int r = 0; r < 32; r++) g_z[(size_t)(l0 + r) * CCH + e] = acc[r];
    }
}

// ---------------- k2: depthwise 3x3x3 conv + bias + SiLU + 3 scan orders ----------------
__global__ __launch_bounds__(256) void k2_conv(const float* __restrict__ conv_w,
                                               const float* __restrict__ conv_b) {
    __shared__ float sin[18 * 18 * 18];
    __shared__ float sout[4096];
    int ch = blockIdx.x, t = threadIdx.x;

    for (int i = t; i < 18 * 18 * 18; i += 256) sin[i] = 0.0f;
    __syncthreads();
    const float* xin = g_xh + (size_t)ch * LTOT;
    for (int s = t; s < 4096; s += 256) {
        int z = s >> 8, y = (s >> 4) & 15, xx = s & 15;
        sin[(z + 1) * 324 + (y + 1) * 18 + (xx + 1)] = xin[s];
    }
    float wr[27];
    #pragma unroll
    for (int i = 0; i < 27; i++) wr[i] = conv_w[ch * 27 + i];
    float bias = conv_b[ch];
    __syncthreads();

    for (int s = t; s < 4096; s += 256) {
        int z = s >> 8, y = (s >> 4) & 15, xx = s & 15;
        float a = bias;
        #pragma unroll
        for (int iz = 0; iz < 3; iz++)
            #pragma unroll
            for (int iy = 0; iy < 3; iy++)
                #pragma unroll
                for (int ix = 0; ix < 3; ix++)
                    a = fmaf(sin[(z + iz) * 324 + (y + iy) * 18 + (xx + ix)], wr[iz * 9 + iy * 3 + ix], a);
        sout[s] = a / (1.0f + __expf(-a));       // SiLU
    }
    __syncthreads();

    float* o0 = g_xs + 0 * (DCH * LTOT) + (size_t)ch * LTOT;
    float* o1 = g_xs + 1 * (DCH * LTOT) + (size_t)ch * LTOT;
    float* o2 = g_xs + 2 * (DCH * LTOT) + (size_t)ch * LTOT;
    for (int l = t; l < 4096; l += 256) {
        o0[l] = sout[l];
        int s1 = ((l & 15) << 8) | ((l >> 8) << 4) | ((l >> 4) & 15);   // order (H,W,D)
        o1[l] = sout[s1];
        int s2 = (((l >> 4) & 15) << 8) | ((l & 15) << 4) | (l >> 8);   // order (W,D,H)
        o2[l] = sout[s2];
    }
}

// ---------------- k4 v4: x_dbl projection, 4c x 4l tile, c split across blocks ----------------
__global__ __launch_bounds__(160) void k4_xdbl() {
    __shared__ float sxs[48][64];
    __shared__ float sw[48][40];
    int kp = blockIdx.y;
    int zh = blockIdx.z;            // c-half: columns zh*40 .. zh*40+39 of padded 80
    int l0 = blockIdx.x * 64;
    int t = threadIdx.x;
    int cg = t % 10;                // c-group within half
    int lg = t / 10;                // 0..15
    int c4 = cg * 4;
    int ls = lg * 4;

    float acc[4][4];
    #pragma unroll
    for (int i = 0; i < 4; i++)
        #pragma unroll
        for (int j = 0; j < 4; j++) acc[i][j] = 0.0f;

    const float* xb = g_xs + (size_t)kp * DCH * LTOT;
    const float* wb = g_wpad + (size_t)kp * DCH * 80 + zh * 40;

    #pragma unroll
    for (int phase = 0; phase < 2; phase++) {
        int d0 = phase * 48;
        for (int i = t; i < 48 * 64; i += 160) {
            int dl = i >> 6, li = i & 63;
            sxs[dl][li] = xb[(size_t)(d0 + dl) * LTOT + l0 + li];
        }
        for (int i = t; i < 48 * 40; i += 160) {
            int dl = i / 40, c = i % 40;
            sw[dl][c] = wb[(size_t)(d0 + dl) * 80 + c];
        }
        __syncthreads();

        #pragma unroll 4
        for (int dl = 0; dl < 48; dl++) {
            float4 wv = *(const float4*)&sw[dl][c4];
            float4 xv = *(const float4*)&sxs[dl][ls];
            acc[0][0] = fmaf(wv.x, xv.x, acc[0][0]);
            acc[0][1] = fmaf(wv.x, xv.y, acc[0][1]);
            acc[0][2] = fmaf(wv.x, xv.z, acc[0][2]);
            acc[0][3] = fmaf(wv.x, xv.w, acc[0][3]);
            acc[1][0] = fmaf(wv.y, xv.x, acc[1][0]);
            acc[1][1] = fmaf(wv.y, xv.y, acc[1][1]);
            acc[1][2] = fmaf(wv.y, xv.z, acc[1][2]);
            acc[1][3] = fmaf(wv.y, xv.w, acc[1][3]);
            acc[2][0] = fmaf(wv.z, xv.x, acc[2][0]);
            acc[2][1] = fmaf(wv.z, xv.y, acc[2][1]);
            acc[2][2] = fmaf(wv.z, xv.z, acc[2][2]);
            acc[2][3] = fmaf(wv.z, xv.w, acc[2][3]);
            acc[3][0] = fmaf(wv.w, xv.x, acc[3][0]);
            acc[3][1] = fmaf(wv.w, xv.y, acc[3][1]);
            acc[3][2] = fmaf(wv.w, xv.z, acc[3][2]);
            acc[3][3] = fmaf(wv.w, xv.w, acc[3][3]);
        }
        __syncthreads();
    }

    // scatter 16 outputs (global padded c; skip pad c >= 76)
    #pragma unroll
    for (int cc = 0; cc < 4; cc++) {
        int c = zh * 40 + c4 + cc;
        if (c < 76) {
            int kk, cf;
            bool fwd;
            if (c < 38) { kk = kp;     cf = c;      fwd = true;  }
            else        { kk = kp + 3; cf = c - 38; fwd = false; }
            float* base;
            int stride, off;
            if (cf < 6)       { base = g_dtr + (size_t)kk * LTOT * RRK; stride = RRK; off = cf; }
            else if (cf < 22) { base = g_Bm  + (size_t)kk * LTOT * NST; stride = NST; off = cf - 6; }
            else              { base = g_Cm  + (size_t)kk * LTOT * NST; stride = NST; off = cf - 22; }
            #pragma unroll
            for (int ll = 0; ll < 4; ll++) {
                int l = l0 + ls + ll;
                int lw = fwd ? l : (4095 - l);
                base[(size_t)lw * stride + off] = acc[cc][ll];
            }
        }
    }
}

// ---------------- k5: dt_proj + softplus, writes paired (dt, xv) as float2 [l][d] ----------------
__global__ __launch_bounds__(128) void k5_dt(const float* __restrict__ dtw,
                                             const float* __restrict__ dtb) {
    int k = blockIdx.y;
    int l0 = blockIdx.x * 16;
    __shared__ float sw[96 * 6];
    __shared__ float sdt[16 * 6];
    __shared__ float sout[16 * 97];
    __shared__ float sx[16 * 97];
    int t = threadIdx.x;

    for (int i = t; i < 576; i += 128) sw[i] = dtw[k * 576 + i];
    if (t < 96) sdt[t] = g_dtr[((size_t)k * LTOT + l0) * RRK + t];
    {
        int kk = (k < 3) ? k : (k - 3);
        const float* xb = g_xs + (size_t)kk * DCH * LTOT;
        bool rev = (k >= 3);
        for (int j = t; j < 96 * 16; j += 128) {
            int d = j >> 4, li = j & 15;
            int lg = rev ? (4095 - (l0 + li)) : (l0 + li);
            sx[li * 97 + d] = xb[(size_t)d * LTOT + lg];
        }
    }
    __syncthreads();

    if (t < 96) {
        float b = dtb[k * 96 + t];
        float acc[16];
        #pragma unroll
        for (int i = 0; i < 16; i++) acc[i] = b;
        #pragma unroll
        for (int r = 0; r < 6; r++) {
            float wv = sw[t * 6 + r];
            #pragma unroll
            for (int i = 0; i < 16; i++) acc[i] = fmaf(wv, sdt[i * 6 + r], acc[i]);
        }
        #pragma unroll
        for (int i = 0; i < 16; i++) {
            float v = acc[i];
            sout[i * 97 + t] = fmaxf(v, 0.0f) + log1pf(__expf(-fabsf(v)));  // softplus
        }
    }
    __syncthreads();

    float2* dp = g_dx + ((size_t)k * LTOT + l0) * DCH;
    for (int j = t; j < 96 * 16; j += 128) {
        int li = j / 96, d = j % 96;
        dp[li * DCH + d] = make_float2(sout[li * 97 + d], sx[li * 97 + d]);
    }
}

// ---------------- k6 v4: 32-chunk 2-pass scan, f16x2-paired ex2, 512 thr ----------------
__global__ __launch_bounds__(512) void k6_scan(const float* __restrict__ D_skip) {
    int k = blockIdx.y;
    int t = threadIdx.x;
    int g = t & 3;                 // n-group: states 4g..4g+3
    int dl = (t >> 2) & 3;
    int d = blockIdx.x * 4 + dl;
    int chunk = t >> 4;            // 0..31
    int lbase = chunk * 128;

    float A2[4];
    #pragma unroll
    for (int j = 0; j < 4; j++)
        A2[j] = g_A2[((size_t)k * DCH + d) * NST + 4 * g + j];

    const float2* dx0 = g_dx + ((size_t)k * LTOT + lbase) * DCH + d;
    const float4* B0  = (const float4*)(g_Bm + ((size_t)k * LTOT + lbase) * NST) + g;
    const float4* C0  = (const float4*)(g_Cm + ((size_t)k * LTOT + lbase) * NST) + g;

    // pass 1: per-chunk (a, b) per state
    float a0 = 1.f, a1 = 1.f, a2 = 1.f, a3 = 1.f;
    float b0 = 0.f, b1 = 0.f, b2 = 0.f, b3 = 0.f;
    {
        const float2* p  = dx0;
        const float4* pb = B0;
        #pragma unroll 4
        for (int i = 0; i < 128; i++) {
            float2 dx = *p;  p += DCH;
            float4 Bv = *pb; pb += 4;
            float dtx = dx.x * dx.y;
            float2 e01 = ex2_pair(dx.x * A2[0], dx.x * A2[1]);
            float2 e23 = ex2_pair(dx.x * A2[2], dx.x * A2[3]);
            b0 = fmaf(e01.x, b0, dtx * Bv.x);  a0 *= e01.x;
            b1 = fmaf(e01.y, b1, dtx * Bv.y);  a1 *= e01.y;
            b2 = fmaf(e23.x, b2, dtx * Bv.z);  a2 *= e23.x;
            b3 = fmaf(e23.y, b3, dtx * Bv.w);  a3 *= e23.y;
        }
    }

    __shared__ float s_a[32][64], s_b[32][64], s_h0[32][64];
    int st = dl * 16 + 4 * g;      // state slot base within block (64 states)
    s_a[chunk][st + 0] = a0;  s_b[chunk][st + 0] = b0;
    s_a[chunk][st + 1] = a1;  s_b[chunk][st + 1] = b1;
    s_a[chunk][st + 2] = a2;  s_b[chunk][st + 2] = b2;
    s_a[chunk][st + 3] = a3;  s_b[chunk][st + 3] = b3;
    __syncthreads();
    if (t < 64) {
        float h = 0.0f;
        #pragma unroll
        for (int ch = 0; ch < 32; ch++) {
            s_h0[ch][t] = h;
            h = fmaf(s_a[ch][t], h, s_b[ch][t]);
        }
    }
    __syncthreads();

    // pass 2: re-scan from chunk prefix, fused y = sum_n h*C + Dskip*xv
    float h0 = s_h0[chunk][st + 0];
    float h1 = s_h0[chunk][st + 1];
    float h2 = s_h0[chunk][st + 2];
    float h3 = s_h0[chunk][st + 3];
    const float Dsk = D_skip[k * 96 + d];
    {
        const float2* p  = dx0;
        const float4* pb = B0;
        const float4* pc = C0;
        float* py = g_ys + ((size_t)k * LTOT + lbase) * DCH + d;
        #pragma unroll 4
        for (int i = 0; i < 128; i++) {
            float2 dx = *p;  p += DCH;
            float4 Bv = *pb; pb += 4;
            float4 Cv = *pc; pc += 4;
            float dtx = dx.x * dx.y;
            float2 e01 = ex2_pair(dx.x * A2[0], dx.x * A2[1]);
            float2 e23 = ex2_pair(dx.x * A2[2], dx.x * A2[3]);
            h0 = fmaf(e01.x, h0, dtx * Bv.x);
            h1 = fmaf(e01.y, h1, dtx * Bv.y);
            h2 = fmaf(e23.x, h2, dtx * Bv.z);
            h3 = fmaf(e23.y, h3, dtx * Bv.w);
            float pacc = h0 * Cv.x;
            pacc = fmaf(h1, Cv.y, pacc);
            pacc = fmaf(h2, Cv.z, pacc);
            pacc = fmaf(h3, Cv.w, pacc);
            pacc += __shfl_xor_sync(0xFFFFFFFFu, pacc, 1);
            pacc += __shfl_xor_sync(0xFFFFFFFFu, pacc, 2);
            if (g == 0) *py = fmaf(Dsk, dx.y, pacc);
            py += DCH;
        }
    }
}

// ---------------- k7: gather 6 directions + LayerNorm(d) + silu(z) gate + out_proj + residual ----------------
__global__ __launch_bounds__(192) void k7_out(const float* __restrict__ x,
                                              const float* __restrict__ onw,
                                              const float* __restrict__ onb,
                                              float* __restrict__ out) {
    __shared__ float sy[16][96];
    __shared__ float sv[16][96];
    int s0 = blockIdx.x * 16;
    int t = threadIdx.x;

    for (int i = t; i < 16 * 96; i += 192) {
        int r = i / 96, d = i % 96;
        int s = s0 + r;
        int dz = s >> 8, hy = (s >> 4) & 15, wx = s & 15;
        int lA = s;
        int lB = (hy << 8) | (wx << 4) | dz;
        int lC = (wx << 8) | (dz << 4) | hy;
        float v = g_ys[((size_t)0 * LTOT + lA) * DCH + d]
                + g_ys[((size_t)1 * LTOT + lB) * DCH + d]
                + g_ys[((size_t)2 * LTOT + lC) * DCH + d]
                + g_ys[((size_t)3 * LTOT + (4095 - lA)) * DCH + d]
                + g_ys[((size_t)4 * LTOT + (4095 - lB)) * DCH + d]
                + g_ys[((size_t)5 * LTOT + (4095 - lC)) * DCH + d];
        sy[r][d] = v;
    }
    __syncthreads();

    int w = t >> 5, lane = t & 31;
    for (int r = w; r < 16; r += 6) {
        float v0 = sy[r][lane], v1 = sy[r][lane + 32], v2 = sy[r][lane + 64];
        float s = v0 + v1 + v2;
        float sq = v0 * v0 + v1 * v1 + v2 * v2;
        #pragma unroll
        for (int o = 16; o; o >>= 1) {
            s += __shfl_xor_sync(0xFFFFFFFFu, s, o);
            sq += __shfl_xor_sync(0xFFFFFFFFu, sq, o);
        }
        float m = s * (1.0f / 96.0f);
        float var = fmaf(-m, m, sq * (1.0f / 96.0f));
        float inv = rsqrtf(var + 1e-5f);
        const float* zr = g_z + (size_t)(s0 + r) * CCH;
        #pragma unroll
        for (int q = 0; q < 3; q++) {
            int c = lane + q * 32;
            float v = (q == 0) ? v0 : ((q == 1) ? v1 : v2);
            float yn = fmaf((v - m) * inv, onw[c], onb[c]);
            float zv = zr[c];
            sv[r][c] = yn * (zv / (1.0f + __expf(-zv)));
        }
    }
    __syncthreads();

    int c = (t < 96) ? t : (t - 96);
    int rbase = (t < 96) ? 0 : 8;
    float acc[8];
    #pragma unroll
    for (int r = 0; r < 8; r++) acc[r] = 0.0f;
    for (int j = 0; j < 96; j += 4) {
        float w0 = g_wot[(j + 0) * 96 + c];
        float w1 = g_wot[(j + 1) * 96 + c];
        float w2 = g_wot[(j + 2) * 96 + c];
        float w3 = g_wot[(j + 3) * 96 + c];
        #pragma unroll
        for (int r = 0; r < 8; r++) {
            float4 yv = *(const float4*)&sv[rbase + r][j];
            acc[r] = fmaf(w0, yv.x, fmaf(w1, yv.y, fmaf(w2, yv.z, fmaf(w3, yv.w, acc[r]))));
        }
    }
    #pragma unroll
    for (int r = 0; r < 8; r++) {
        int s = s0 + rbase + r;
        out[(size_t)s * CCH + c] = x[(size_t)s * CCH + c] + acc[r];
    }
}

// ---------------- launch ----------------
extern "C" void kernel_launch(void* const* d_in, const int* in_sizes, int n_in,
                              void* d_out, int out_size) {
    const float* x         = (const float*)d_in[0];
    const float* ln1_w     = (const float*)d_in[1];
    const float* ln1_b     = (const float*)d_in[2];
    const float* in_proj_w = (const float*)d_in[3];
    const float* conv_w    = (const float*)d_in[4];
    const float* conv_b    = (const float*)d_in[5];
    const float* x_proj_w  = (const float*)d_in[6];
    const float* dt_proj_w = (const float*)d_in[7];
    const float* dt_proj_b = (const float*)d_in[8];
    const float* A_log     = (const float*)d_in[9];
    const float* D_skip    = (const float*)d_in[10];
    const float* out_nw    = (const float*)d_in[11];
    const float* out_nb    = (const float*)d_in[12];
    const float* out_pw    = (const float*)d_in[13];
    float* out = (float*)d_out;

    k0_prep<<<96, 256>>>(in_proj_w, x_proj_w, A_log, out_pw);
    k1_ln_inproj<<<128, 192>>>(x, ln1_w, ln1_b);
    k2_conv<<<96, 256>>>(conv_w, conv_b);
    k4_xdbl<<<dim3(64, 3, 2), 160>>>();
    k5_dt<<<dim3(256, 6), 128>>>(dt_proj_w, dt_proj_b);
    k6_scan<<<dim3(24, 6), 512>>>(D_skip);
    k7_out<<<256, 192>>>(x, out_nw, out_nb, out);
}

// round 11
// speedup vs baseline: 1.0169x; 1.0169x over previous
#include <cuda_runtime.h>
#include <math.h>

#define LTOT 4096
#define CCH  96
#define DCH  96
#define KDIR 6
#define NST  16
#define RRK  6

__device__ __forceinline__ float ex2_fast(float x) {
    float r;
    asm("ex2.approx.ftz.f32 %0, %1;" : "=f"(r) : "f"(x));
    return r;
}

// ---------------- scratch (device globals; no allocation allowed) ----------------
__device__ float g_wint[CCH * 192];          // in_proj_w transposed [c][e]
__device__ float g_wpad[3 * DCH * 80];       // x_proj_w fused pairs, padded [k'][d][80]
__device__ float g_A2[KDIR * DCH * NST];     // -exp(A_log) * log2(e)
__device__ float g_wot[DCH * CCH];           // out_proj_w transposed [e][c]
__device__ float g_xh[DCH * LTOT];           // conv input  [ch][s]
__device__ float g_z[LTOT * CCH];            // gate        [s][e]
__device__ float g_xs[3 * DCH * LTOT];       // scan inputs [k'][d][l]
__device__ float g_dtr[KDIR * LTOT * RRK];   // raw dt      [k][l][r]
__device__ float g_BC[KDIR * LTOT * 32];     // B(n 0..15) | C(n 0..15) interleaved [k][l][32]
__device__ float2 g_dx[KDIR * LTOT * DCH];   // (softplus dt, flip-applied xs) [k][l][d]
__device__ float g_ys[KDIR * LTOT * DCH];    // scan output [k][l][d]

// ---------------- prep: weight transposes + A2 = -exp(A_log)*log2e ----------------
__global__ void k0_prep(const float* __restrict__ in_proj_w,
                        const float* __restrict__ x_proj_w,
                        const float* __restrict__ A_log,
                        const float* __restrict__ out_proj_w) {
    int i = blockIdx.x * blockDim.x + threadIdx.x;
    if (i < CCH * 192) {                       // g_wint[c][e] = in_proj_w[e][c]
        int c = i / 192, e = i % 192;
        g_wint[i] = in_proj_w[e * CCH + c];
    }
    if (i < 3 * DCH * 80) {                    // fused+padded weights [kp][d][80]
        int kp = i / (DCH * 80);
        int rem = i % (DCH * 80);
        int d = rem / 80, c = rem % 80;
        float v = 0.0f;
        if (c < 76) {
            int kk = (c < 38) ? kp : kp + 3;
            int cc = (c < 38) ? c : c - 38;
            v = x_proj_w[(kk * 38 + cc) * DCH + d];
        }
        g_wpad[i] = v;
    }
    if (i < KDIR * DCH * NST) g_A2[i] = -expf(A_log[i]) * 1.4426950408889634f;
    if (i < DCH * CCH) {                       // g_wot[e][c] = out_proj_w[c][e]
        int e = i / CCH, c = i % CCH;
        g_wot[i] = out_proj_w[c * DCH + e];
    }
}

// ---------------- k1: LayerNorm(C=96) + in_proj (96 -> 192), split xh/z ----------------
__global__ __launch_bounds__(192) void k1_ln_inproj(const float* __restrict__ x,
                                                    const float* __restrict__ lw,
                                                    const float* __restrict__ lb) {
    __shared__ float sxn[16][96];
    int l0 = blockIdx.x * 16;
    int t = threadIdx.x, w = t >> 5, lane = t & 31;

    for (int r = w; r < 16; r += 6) {
        const float* xr = x + (size_t)(l0 + r) * CCH;
        float v0 = xr[lane], v1 = xr[lane + 32], v2 = xr[lane + 64];
        float s = v0 + v1 + v2;
        float sq = v0 * v0 + v1 * v1 + v2 * v2;
        #pragma unroll
        for (int o = 16; o; o >>= 1) {
            s += __shfl_xor_sync(0xFFFFFFFFu, s, o);
            sq += __shfl_xor_sync(0xFFFFFFFFu, sq, o);
        }
        float m = s * (1.0f / 96.0f);
        float var = fmaf(-m, m, sq * (1.0f / 96.0f));
        float inv = rsqrtf(var + 1e-6f);
        sxn[r][lane]      = fmaf((v0 - m) * inv, lw[lane],      lb[lane]);
        sxn[r][lane + 32] = fmaf((v1 - m) * inv, lw[lane + 32], lb[lane + 32]);
        sxn[r][lane + 64] = fmaf((v2 - m) * inv, lw[lane + 64], lb[lane + 64]);
    }
    __syncthreads();

    float acc[16];
    #pragma unroll
    for (int r = 0; r < 16; r++) acc[r] = 0.0f;
    for (int j = 0; j < 96; j += 4) {
        float w0 = g_wint[(j + 0) * 192 + t];
        float w1 = g_wint[(j + 1) * 192 + t];
        float w2 = g_wint[(j + 2) * 192 + t];
        float w3 = g_wint[(j + 3) * 192 + t];
        #pragma unroll
        for (int r = 0; r < 16; r++) {
            float4 xv = *(const float4*)&sxn[r][j];
            acc[r] = fmaf(w0, xv.x, fmaf(w1, xv.y, fmaf(w2, xv.z, fmaf(w3, xv.w, acc[r]))));
        }
    }
    if (t < 96) {
        float* o = g_xh + (size_t)t * LTOT + l0;
        #pragma unroll
        for (int r = 0; r < 16; r += 4)
            *(float4*)&o[r] = make_float4(acc[r], acc[r + 1], acc[r + 2], acc[r + 3]);
    } else {
        int e = t - 96;
        #pragma unroll
        for (int r = 0; r < 16; r++) g_z[(size_t)(l0 + r) * CCH + e] = acc[r];
    }
}

// ---------------- k2 v2: depthwise conv split by z-halves, 192 blocks ----------------
// block = (channel, z-half): 16x16x8 output slab + 10-plane halo. smem ~21KB.
__global__ __launch_bounds__(256) void k2_conv(const float* __restrict__ conv_w,
                                               const float* __restrict__ conv_b) {
    __shared__ float sin[10 * 324];
    __shared__ float sout[2048];
    int ch = blockIdx.x, zh = blockIdx.y, t = threadIdx.x;
    int z0 = zh << 3;

    for (int i = t; i < 10 * 324; i += 256) sin[i] = 0.0f;
    __syncthreads();
    const float* xin = g_xh + (size_t)ch * LTOT;
    for (int i = t; i < 10 * 256; i += 256) {
        int p = i >> 8, yx = i & 255;
        int gz = z0 - 1 + p;
        if (gz >= 0 && gz < 16) {
            int y = yx >> 4, xx = yx & 15;
            sin[p * 324 + (y + 1) * 18 + (xx + 1)] = xin[(gz << 8) | yx];
        }
    }
    float wr[27];
    #pragma unroll
    for (int i = 0; i < 27; i++) wr[i] = conv_w[ch * 27 + i];
    float bias = conv_b[ch];
    __syncthreads();

    for (int s = t; s < 2048; s += 256) {
        int zl = s >> 8, y = (s >> 4) & 15, xx = s & 15;
        float a = bias;
        #pragma unroll
        for (int iz = 0; iz < 3; iz++)
            #pragma unroll
            for (int iy = 0; iy < 3; iy++)
                #pragma unroll
                for (int ix = 0; ix < 3; ix++)
                    a = fmaf(sin[(zl + iz) * 324 + (y + iy) * 18 + (xx + ix)], wr[iz * 9 + iy * 3 + ix], a);
        sout[s] = a / (1.0f + __expf(-a));       // SiLU
    }
    __syncthreads();

    float* o0 = g_xs + 0 * (DCH * LTOT) + (size_t)ch * LTOT;
    float* o1 = g_xs + 1 * (DCH * LTOT) + (size_t)ch * LTOT;
    float* o2 = g_xs + 2 * (DCH * LTOT) + (size_t)ch * LTOT;
    // o0: identity order, contiguous
    for (int s = t; s < 2048; s += 256) o0[(z0 << 8) + s] = sout[s];
    // o1[l] = full[(lx,lz,ly)] : our slab owns l with (l&15) in [z0, z0+8)
    for (int i = t; i < 2048; i += 256) {
        int lxd = z0 + (i & 7);
        int hi = i >> 3;
        int lzd = hi >> 4, lyd = hi & 15;
        o1[(lzd << 8) | (lyd << 4) | lxd] = sout[((i & 7) << 8) | (lzd << 4) | lyd];
    }
    // o2[l] = full[(ly,lx,lz)] : our slab owns l with ((l>>4)&15) in [z0, z0+8)
    for (int i = t; i < 2048; i += 256) {
        int lzd = i >> 7;
        int lyd = z0 + ((i >> 4) & 7);
        int lxd = i & 15;
        o2[(lzd << 8) | (lyd << 4) | lxd] = sout[(((i >> 4) & 7) << 8) | (lxd << 4) | lzd];
    }
}

// ---------------- k4 v4: x_dbl projection, 4c x 4l tile, c split across blocks ----------------
__global__ __launch_bounds__(160) void k4_xdbl() {
    __shared__ float sxs[48][64];
    __shared__ float sw[48][40];
    int kp = blockIdx.y;
    int zh = blockIdx.z;            // c-half: columns zh*40 .. zh*40+39 of padded 80
    int l0 = blockIdx.x * 64;
    int t = threadIdx.x;
    int cg = t % 10;                // c-group within half
    int lg = t / 10;                // 0..15
    int c4 = cg * 4;
    int ls = lg * 4;

    float acc[4][4];
    #pragma unroll
    for (int i = 0; i < 4; i++)
        #pragma unroll
        for (int j = 0; j < 4; j++) acc[i][j] = 0.0f;

    const float* xb = g_xs + (size_t)kp * DCH * LTOT;
    const float* wb = g_wpad + (size_t)kp * DCH * 80 + zh * 40;

    #pragma unroll
    for (int phase = 0; phase < 2; phase++) {
        int d0 = phase * 48;
        for (int i = t; i < 48 * 64; i += 160) {
            int dl = i >> 6, li = i & 63;
            sxs[dl][li] = xb[(size_t)(d0 + dl) * LTOT + l0 + li];
        }
        for (int i = t; i < 48 * 40; i += 160) {
            int dl = i / 40, c = i % 40;
            sw[dl][c] = wb[(size_t)(d0 + dl) * 80 + c];
        }
        __syncthreads();

        #pragma unroll 4
        for (int dl = 0; dl < 48; dl++) {
            float4 wv = *(const float4*)&sw[dl][c4];
            float4 xv = *(const float4*)&sxs[dl][ls];
            acc[0][0] = fmaf(wv.x, xv.x, acc[0][0]);
            acc[0][1] = fmaf(wv.x, xv.y, acc[0][1]);
            acc[0][2] = fmaf(wv.x, xv.z, acc[0][2]);
            acc[0][3] = fmaf(wv.x, xv.w, acc[0][3]);
            acc[1][0] = fmaf(wv.y, xv.x, acc[1][0]);
            acc[1][1] = fmaf(wv.y, xv.y, acc[1][1]);
            acc[1][2] = fmaf(wv.y, xv.z, acc[1][2]);
            acc[1][3] = fmaf(wv.y, xv.w, acc[1][3]);
            acc[2][0] = fmaf(wv.z, xv.x, acc[2][0]);
            acc[2][1] = fmaf(wv.z, xv.y, acc[2][1]);
            acc[2][2] = fmaf(wv.z, xv.z, acc[2][2]);
            acc[2][3] = fmaf(wv.z, xv.w, acc[2][3]);
            acc[3][0] = fmaf(wv.w, xv.x, acc[3][0]);
            acc[3][1] = fmaf(wv.w, xv.y, acc[3][1]);
            acc[3][2] = fmaf(wv.w, xv.z, acc[3][2]);
            acc[3][3] = fmaf(wv.w, xv.w, acc[3][3]);
        }
        __syncthreads();
    }

    // scatter 16 outputs (global padded c; skip pad c >= 76)
    #pragma unroll
    for (int cc = 0; cc < 4; cc++) {
        int c = zh * 40 + c4 + cc;
        if (c < 76) {
            int kk, cf;
            bool fwd;
            if (c < 38) { kk = kp;     cf = c;      fwd = true;  }
            else        { kk = kp + 3; cf = c - 38; fwd = false; }
            float* base;
            int stride, off;
            if (cf < 6)       { base = g_dtr + (size_t)kk * LTOT * RRK; stride = RRK; off = cf; }
            else if (cf < 22) { base = g_BC  + (size_t)kk * LTOT * 32;  stride = 32;  off = cf - 6; }
            else              { base = g_BC  + (size_t)kk * LTOT * 32;  stride = 32;  off = 16 + (cf - 22); }
            #pragma unroll
            for (int ll = 0; ll < 4; ll++) {
                int l = l0 + ls + ll;
                int lw = fwd ? l : (4095 - l);
                base[(size_t)lw * stride + off] = acc[cc][ll];
            }
        }
    }
}

// ---------------- k5: dt_proj + softplus, writes paired (dt, xv) as float2 [l][d] ----------------
__global__ __launch_bounds__(128) void k5_dt(const float* __restrict__ dtw,
                                             const float* __restrict__ dtb) {
    int k = blockIdx.y;
    int l0 = blockIdx.x * 16;
    __shared__ float sw[96 * 6];
    __shared__ float sdt[16 * 6];
    __shared__ float sout[16 * 97];
    __shared__ float sx[16 * 97];
    int t = threadIdx.x;

    for (int i = t; i < 576; i += 128) sw[i] = dtw[k * 576 + i];
    if (t < 96) sdt[t] = g_dtr[((size_t)k * LTOT + l0) * RRK + t];
    {
        int kk = (k < 3) ? k : (k - 3);
        const float* xb = g_xs + (size_t)kk * DCH * LTOT;
        bool rev = (k >= 3);
        for (int j = t; j < 96 * 16; j += 128) {
            int d = j >> 4, li = j & 15;
            int lg = rev ? (4095 - (l0 + li)) : (l0 + li);
            sx[li * 97 + d] = xb[(size_t)d * LTOT + lg];
        }
    }
    __syncthreads();

    if (t < 96) {
        float b = dtb[k * 96 + t];
        float acc[16];
        #pragma unroll
        for (int i = 0; i < 16; i++) acc[i] = b;
        #pragma unroll
        for (int r = 0; r < 6; r++) {
            float wv = sw[t * 6 + r];
            #pragma unroll
            for (int i = 0; i < 16; i++) acc[i] = fmaf(wv, sdt[i * 6 + r], acc[i]);
        }
        #pragma unroll
        for (int i = 0; i < 16; i++) {
            float v = acc[i];
            sout[i * 97 + t] = fmaxf(v, 0.0f) + log1pf(__expf(-fabsf(v)));  // softplus
        }
    }
    __syncthreads();

    float2* dp = g_dx + ((size_t)k * LTOT + l0) * DCH;
    for (int j = t; j < 96 * 16; j += 128) {
        int li = j / 96, d = j % 96;
        dp[li * DCH + d] = make_float2(sout[li * 97 + d], sx[li * 97 + d]);
    }
}

// ---------------- k6 v5: 32-chunk 2-pass scan, scalar ex2, interleaved BC ----------------
__global__ __launch_bounds__(512) void k6_scan(const float* __restrict__ D_skip) {
    int k = blockIdx.y;
    int t = threadIdx.x;
    int g = t & 3;                 // n-group: states 4g..4g+3
    int dl = (t >> 2) & 3;
    int d = blockIdx.x * 4 + dl;
    int chunk = t >> 4;            // 0..31
    int lbase = chunk * 128;

    float A2[4];
    #pragma unroll
    for (int j = 0; j < 4; j++)
        A2[j] = g_A2[((size_t)k * DCH + d) * NST + 4 * g + j];

    const float2* dx0 = g_dx + ((size_t)k * LTOT + lbase) * DCH + d;
    const float4* BC0 = (const float4*)(g_BC + ((size_t)k * LTOT + lbase) * 32) + g;

    // pass 1: per-chunk (a, b) per state; a_j = exp2(A2_j * sum(dt))
    float sdt = 0.f;
    float b0 = 0.f, b1 = 0.f, b2 = 0.f, b3 = 0.f;
    {
        const float2* p   = dx0;
        const float4* pbc = BC0;
        #pragma unroll 4
        for (int i = 0; i < 128; i++) {
            float2 dx = *p;   p += DCH;
            float4 Bv = *pbc; pbc += 8;
            float dtx = dx.x * dx.y;
            float e0 = ex2_fast(dx.x * A2[0]);
            float e1 = ex2_fast(dx.x * A2[1]);
            float e2 = ex2_fast(dx.x * A2[2]);
            float e3 = ex2_fast(dx.x * A2[3]);
            b0 = fmaf(e0, b0, dtx * Bv.x);
            b1 = fmaf(e1, b1, dtx * Bv.y);
            b2 = fmaf(e2, b2, dtx * Bv.z);
            b3 = fmaf(e3, b3, dtx * Bv.w);
            sdt += dx.x;
        }
    }
    float a0 = ex2_fast(A2[0] * sdt);
    float a1 = ex2_fast(A2[1] * sdt);
    float a2 = ex2_fast(A2[2] * sdt);
    float a3 = ex2_fast(A2[3] * sdt);

    __shared__ float s_a[32][64], s_b[32][64], s_h0[32][64];
    int st = dl * 16 + 4 * g;      // state slot base within block (64 states)
    s_a[chunk][st + 0] = a0;  s_b[chunk][st + 0] = b0;
    s_a[chunk][st + 1] = a1;  s_b[chunk][st + 1] = b1;
    s_a[chunk][st + 2] = a2;  s_b[chunk][st + 2] = b2;
    s_a[chunk][st + 3] = a3;  s_b[chunk][st + 3] = b3;
    __syncthreads();
    if (t < 64) {
        float h = 0.0f;
        #pragma unroll
        for (int ch = 0; ch < 32; ch++) {
            s_h0[ch][t] = h;
            h = fmaf(s_a[ch][t], h, s_b[ch][t]);
        }
    }
    __syncthreads();

    // pass 2: re-scan from chunk prefix, fused y = sum_n h*C + Dskip*xv
    float h0 = s_h0[chunk][st + 0];
    float h1 = s_h0[chunk][st + 1];
    float h2 = s_h0[chunk][st + 2];
    float h3 = s_h0[chunk][st + 3];
    const float Dsk = D_skip[k * 96 + d];
    {
        const float2* p   = dx0;
        const float4* pbc = BC0;
        float* py = g_ys + ((size_t)k * LTOT + lbase) * DCH + d;
        #pragma unroll 4
        for (int i = 0; i < 128; i++) {
            float2 dx = *p;   p += DCH;
            float4 Bv = pbc[0];
            float4 Cv = pbc[4];
            pbc += 8;
            float dtx = dx.x * dx.y;
            float e0 = ex2_fast(dx.x * A2[0]);
            float e1 = ex2_fast(dx.x * A2[1]);
            float e2 = ex2_fast(dx.x * A2[2]);
            float e3 = ex2_fast(dx.x * A2[3]);
            h0 = fmaf(e0, h0, dtx * Bv.x);
            h1 = fmaf(e1, h1, dtx * Bv.y);
            h2 = fmaf(e2, h2, dtx * Bv.z);
            h3 = fmaf(e3, h3, dtx * Bv.w);
            float pacc = h0 * Cv.x;
            pacc = fmaf(h1, Cv.y, pacc);
            pacc = fmaf(h2, Cv.z, pacc);
            pacc = fmaf(h3, Cv.w, pacc);
            pacc += __shfl_xor_sync(0xFFFFFFFFu, pacc, 1);
            pacc += __shfl_xor_sync(0xFFFFFFFFu, pacc, 2);
            if (g == 0) *py = fmaf(Dsk, dx.y, pacc);
            py += DCH;
        }
    }
}

// ---------------- k7: gather 6 directions + LayerNorm(d) + silu(z) gate + out_proj + residual ----------------
__global__ __launch_bounds__(192) void k7_out(const float* __restrict__ x,
                                              const float* __restrict__ onw,
                                              const float* __restrict__ onb,
                                              float* __restrict__ out) {
    __shared__ float sy[16][96];
    __shared__ float sv[16][96];
    int s0 = blockIdx.x * 16;
    int t = threadIdx.x;

    for (int i = t; i < 16 * 96; i += 192) {
        int r = i / 96, d = i % 96;
        int s = s0 + r;
        int dz = s >> 8, hy = (s >> 4) & 15, wx = s & 15;
        int lA = s;
        int lB = (hy << 8) | (wx << 4) | dz;
        int lC = (wx << 8) | (dz << 4) | hy;
        float v = g_ys[((size_t)0 * LTOT + lA) * DCH + d]
                + g_ys[((size_t)1 * LTOT + lB) * DCH + d]
                + g_ys[((size_t)2 * LTOT + lC) * DCH + d]
                + g_ys[((size_t)3 * LTOT + (4095 - lA)) * DCH + d]
                + g_ys[((size_t)4 * LTOT + (4095 - lB)) * DCH + d]
                + g_ys[((size_t)5 * LTOT + (4095 - lC)) * DCH + d];
        sy[r][d] = v;
    }
    __syncthreads();

    int w = t >> 5, lane = t & 31;
    for (int r = w; r < 16; r += 6) {
        float v0 = sy[r][lane], v1 = sy[r][lane + 32], v2 = sy[r][lane + 64];
        float s = v0 + v1 + v2;
        float sq = v0 * v0 + v1 * v1 + v2 * v2;
        #pragma unroll
        for (int o = 16; o; o >>= 1) {
            s += __shfl_xor_sync(0xFFFFFFFFu, s, o);
            sq += __shfl_xor_sync(0xFFFFFFFFu, sq, o);
        }
        float m = s * (1.0f / 96.0f);
        float var = fmaf(-m, m, sq * (1.0f / 96.0f));
        float inv = rsqrtf(var + 1e-5f);
        const float* zr = g_z + (size_t)(s0 + r) * CCH;
        #pragma unroll
        for (int q = 0; q < 3; q++) {
            int c = lane + q * 32;
            float v = (q == 0) ? v0 : ((q == 1) ? v1 : v2);
            float yn = fmaf((v - m) * inv, onw[c], onb[c]);
            float zv = zr[c];
            sv[r][c] = yn * (zv / (1.0f + __expf(-zv)));
        }
    }
    __syncthreads();

    int c = (t < 96) ? t : (t - 96);
    int rbase = (t < 96) ? 0 : 8;
    float acc[8];
    #pragma unroll
    for (int r = 0; r < 8; r++) acc[r] = 0.0f;
    for (int j = 0; j < 96; j += 4) {
        float w0 = g_wot[(j + 0) * 96 + c];
        float w1 = g_wot[(j + 1) * 96 + c];
        float w2 = g_wot[(j + 2) * 96 + c];
        float w3 = g_wot[(j + 3) * 96 + c];
        #pragma unroll
        for (int r = 0; r < 8; r++) {
            float4 yv = *(const float4*)&sv[rbase + r][j];
            acc[r] = fmaf(w0, yv.x, fmaf(w1, yv.y, fmaf(w2, yv.z, fmaf(w3, yv.w, acc[r]))));
        }
    }
    #pragma unroll
    for (int r = 0; r < 8; r++) {
        int s = s0 + rbase + r;
        out[(size_t)s * CCH + c] = x[(size_t)s * CCH + c] + acc[r];
    }
}

// ---------------- launch ----------------
extern "C" void kernel_launch(void* const* d_in, const int* in_sizes, int n_in,
                              void* d_out, int out_size) {
    const float* x         = (const float*)d_in[0];
    const float* ln1_w     = (const float*)d_in[1];
    const float* ln1_b     = (const float*)d_in[2];
    const float* in_proj_w = (const float*)d_in[3];
    const float* conv_w    = (const float*)d_in[4];
    const float* conv_b    = (const float*)d_in[5];
    const float* x_proj_w  = (const float*)d_in[6];
    const float* dt_proj_w = (const float*)d_in[7];
    const float* dt_proj_b = (const float*)d_in[8];
    const float* A_log     = (const float*)d_in[9];
    const float* D_skip    = (const float*)d_in[10];
    const float* out_nw    = (const float*)d_in[11];
    const float* out_nb    = (const float*)d_in[12];
    const float* out_pw    = (const float*)d_in[13];
    float* out = (float*)d_out;

    k0_prep<<<96, 256>>>(in_proj_w, x_proj_w, A_log, out_pw);
    k1_ln_inproj<<<256, 192>>>(x, ln1_w, ln1_b);
    k2_conv<<<dim3(96, 2), 256>>>(conv_w, conv_b);
    k4_xdbl<<<dim3(64, 3, 2), 160>>>();
    k5_dt<<<dim3(256, 6), 128>>>(dt_proj_w, dt_proj_b);
    k6_scan<<<dim3(24, 6), 512>>>(D_skip);
    k7_out<<<256, 192>>>(x, out_nw, out_nb, out);
}

// round 12
// speedup vs baseline: 1.3553x; 1.3328x over previous
#include <cuda_runtime.h>
#include <math.h>

#define LTOT 4096
#define CCH  96
#define DCH  96
#define KDIR 6
#define NST  16
#define RRK  6

__device__ __forceinline__ float ex2_fast(float x) {
    float r;
    asm("ex2.approx.ftz.f32 %0, %1;" : "=f"(r) : "f"(x));
    return r;
}

// ---------------- scratch (device globals; no allocation allowed) ----------------
__device__ float g_wint[CCH * 192];          // in_proj_w transposed [c][e]
__device__ float g_wpad[3 * DCH * 80];       // x_proj_w fused pairs, padded [k'][d][80]
__device__ float g_A2[KDIR * DCH * NST];     // -exp(A_log) * log2(e)
__device__ float g_wot[DCH * CCH];           // out_proj_w transposed [e][c]
__device__ float g_xh[DCH * LTOT];           // conv input  [ch][s]
__device__ float g_z[LTOT * CCH];            // gate        [s][e]
__device__ float g_xs[3 * DCH * LTOT];       // scan inputs [k'][d][l]
__device__ float g_dtr[KDIR * LTOT * RRK];   // raw dt      [k][l][r]
__device__ float g_Bm[KDIR * LTOT * NST];    // B           [k][l][n]
__device__ float g_Cm[KDIR * LTOT * NST];    // C           [k][l][n]
__device__ float2 g_dx[KDIR * LTOT * DCH];   // (softplus dt, flip-applied xs) [k][l][d]
__device__ float g_ys[KDIR * LTOT * DCH];    // scan output [k][l][d]

// ---------------- prep: weight transposes + A2 = -exp(A_log)*log2e ----------------
__global__ void k0_prep(const float* __restrict__ in_proj_w,
                        const float* __restrict__ x_proj_w,
                        const float* __restrict__ A_log,
                        const float* __restrict__ out_proj_w) {
    int i = blockIdx.x * blockDim.x + threadIdx.x;
    if (i < CCH * 192) {                       // g_wint[c][e] = in_proj_w[e][c]
        int c = i / 192, e = i % 192;
        g_wint[i] = in_proj_w[e * CCH + c];
    }
    if (i < 3 * DCH * 80) {                    // fused+padded weights [kp][d][80]
        int kp = i / (DCH * 80);
        int rem = i % (DCH * 80);
        int d = rem / 80, c = rem % 80;
        float v = 0.0f;
        if (c < 76) {
            int kk = (c < 38) ? kp : kp + 3;
            int cc = (c < 38) ? c : c - 38;
            v = x_proj_w[(kk * 38 + cc) * DCH + d];
        }
        g_wpad[i] = v;
    }
    if (i < KDIR * DCH * NST) g_A2[i] = -expf(A_log[i]) * 1.4426950408889634f;
    if (i < DCH * CCH) {                       // g_wot[e][c] = out_proj_w[c][e]
        int e = i / CCH, c = i % CCH;
        g_wot[i] = out_proj_w[c * DCH + e];
    }
}

// ---------------- k1: LayerNorm(C=96) + in_proj (96 -> 192), split xh/z ----------------
__global__ __launch_bounds__(192) void k1_ln_inproj(const float* __restrict__ x,
                                                    const float* __restrict__ lw,
                                                    const float* __restrict__ lb) {
    __shared__ float sxn[16][96];
    int l0 = blockIdx.x * 16;
    int t = threadIdx.x, w = t >> 5, lane = t & 31;

    for (int r = w; r < 16; r += 6) {
        const float* xr = x + (size_t)(l0 + r) * CCH;
        float v0 = xr[lane], v1 = xr[lane + 32], v2 = xr[lane + 64];
        float s = v0 + v1 + v2;
        float sq = v0 * v0 + v1 * v1 + v2 * v2;
        #pragma unroll
        for (int o = 16; o; o >>= 1) {
            s += __shfl_xor_sync(0xFFFFFFFFu, s, o);
            sq += __shfl_xor_sync(0xFFFFFFFFu, sq, o);
        }
        float m = s * (1.0f / 96.0f);
        float var = fmaf(-m, m, sq * (1.0f / 96.0f));
        float inv = rsqrtf(var + 1e-6f);
        sxn[r][lane]      = fmaf((v0 - m) * inv, lw[lane],      lb[lane]);
        sxn[r][lane + 32] = fmaf((v1 - m) * inv, lw[lane + 32], lb[lane + 32]);
        sxn[r][lane + 64] = fmaf((v2 - m) * inv, lw[lane + 64], lb[lane + 64]);
    }
    __syncthreads();

    float acc[16];
    #pragma unroll
    for (int r = 0; r < 16; r++) acc[r] = 0.0f;
    for (int j = 0; j < 96; j += 4) {
        float w0 = g_wint[(j + 0) * 192 + t];
        float w1 = g_wint[(j + 1) * 192 + t];
        float w2 = g_wint[(j + 2) * 192 + t];
        float w3 = g_wint[(j + 3) * 192 + t];
        #pragma unroll
        for (int r = 0; r < 16; r++) {
            float4 xv = *(const float4*)&sxn[r][j];
            acc[r] = fmaf(w0, xv.x, fmaf(w1, xv.y, fmaf(w2, xv.z, fmaf(w3, xv.w, acc[r]))));
        }
    }
    if (t < 96) {
        float* o = g_xh + (size_t)t * LTOT + l0;
        #pragma unroll
        for (int r = 0; r < 16; r += 4)
            *(float4*)&o[r] = make_float4(acc[r], acc[r + 1], acc[r + 2], acc[r + 3]);
    } else {
        int e = t - 96;
        #pragma unroll
        for (int r = 0; r < 16; r++) g_z[(size_t)(l0 + r) * CCH + e] = acc[r];
    }
}

// ---------------- k2: depthwise 3x3x3 conv + bias + SiLU + 3 scan orders ----------------
__global__ __launch_bounds__(256) void k2_conv(const float* __restrict__ conv_w,
                                               const float* __restrict__ conv_b) {
    __shared__ float sin[18 * 18 * 18];
    __shared__ float sout[4096];
    int ch = blockIdx.x, t = threadIdx.x;

    for (int i = t; i < 18 * 18 * 18; i += 256) sin[i] = 0.0f;
    __syncthreads();
    const float* xin = g_xh + (size_t)ch * LTOT;
    for (int s = t; s < 4096; s += 256) {
        int z = s >> 8, y = (s >> 4) & 15, xx = s & 15;
        sin[(z + 1) * 324 + (y + 1) * 18 + (xx + 1)] = xin[s];
    }
    float wr[27];
    #pragma unroll
    for (int i = 0; i < 27; i++) wr[i] = conv_w[ch * 27 + i];
    float bias = conv_b[ch];
    __syncthreads();

    for (int s = t; s < 4096; s += 256) {
        int z = s >> 8, y = (s >> 4) & 15, xx = s & 15;
        float a = bias;
        #pragma unroll
        for (int iz = 0; iz < 3; iz++)
            #pragma unroll
            for (int iy = 0; iy < 3; iy++)
                #pragma unroll
                for (int ix = 0; ix < 3; ix++)
                    a = fmaf(sin[(z + iz) * 324 + (y + iy) * 18 + (xx + ix)], wr[iz * 9 + iy * 3 + ix], a);
        sout[s] = a / (1.0f + __expf(-a));       // SiLU
    }
    __syncthreads();

    float* o0 = g_xs + 0 * (DCH * LTOT) + (size_t)ch * LTOT;
    float* o1 = g_xs + 1 * (DCH * LTOT) + (size_t)ch * LTOT;
    float* o2 = g_xs + 2 * (DCH * LTOT) + (size_t)ch * LTOT;
    for (int l = t; l < 4096; l += 256) {
        o0[l] = sout[l];
        int s1 = ((l & 15) << 8) | ((l >> 8) << 4) | ((l >> 4) & 15);   // order (H,W,D)
        o1[l] = sout[s1];
        int s2 = (((l >> 4) & 15) << 8) | ((l & 15) << 4) | (l >> 8);   // order (W,D,H)
        o2[l] = sout[s2];
    }
}

// ---------------- k4 v4: x_dbl projection, 4c x 4l tile, c split across blocks ----------------
__global__ __launch_bounds__(160) void k4_xdbl() {
    __shared__ float sxs[48][64];
    __shared__ float sw[48][40];
    int kp = blockIdx.y;
    int zh = blockIdx.z;            // c-half: columns zh*40 .. zh*40+39 of padded 80
    int l0 = blockIdx.x * 64;
    int t = threadIdx.x;
    int cg = t % 10;                // c-group within half
    int lg = t / 10;                // 0..15
    int c4 = cg * 4;
    int ls = lg * 4;

    float acc[4][4];
    #pragma unroll
    for (int i = 0; i < 4; i++)
        #pragma unroll
        for (int j = 0; j < 4; j++) acc[i][j] = 0.0f;

    const float* xb = g_xs + (size_t)kp * DCH * LTOT;
    const float* wb = g_wpad + (size_t)kp * DCH * 80 + zh * 40;

    #pragma unroll
    for (int phase = 0; phase < 2; phase++) {
        int d0 = phase * 48;
        for (int i = t; i < 48 * 64; i += 160) {
            int dl = i >> 6, li = i & 63;
            sxs[dl][li] = xb[(size_t)(d0 + dl) * LTOT + l0 + li];
        }
        for (int i = t; i < 48 * 40; i += 160) {
            int dl = i / 40, c = i % 40;
            sw[dl][c] = wb[(size_t)(d0 + dl) * 80 + c];
        }
        __syncthreads();

        #pragma unroll 4
        for (int dl = 0; dl < 48; dl++) {
            float4 wv = *(const float4*)&sw[dl][c4];
            float4 xv = *(const float4*)&sxs[dl][ls];
            acc[0][0] = fmaf(wv.x, xv.x, acc[0][0]);
            acc[0][1] = fmaf(wv.x, xv.y, acc[0][1]);
            acc[0][2] = fmaf(wv.x, xv.z, acc[0][2]);
            acc[0][3] = fmaf(wv.x, xv.w, acc[0][3]);
            acc[1][0] = fmaf(wv.y, xv.x, acc[1][0]);
            acc[1][1] = fmaf(wv.y, xv.y, acc[1][1]);
            acc[1][2] = fmaf(wv.y, xv.z, acc[1][2]);
            acc[1][3] = fmaf(wv.y, xv.w, acc[1][3]);
            acc[2][0] = fmaf(wv.z, xv.x, acc[2][0]);
            acc[2][1] = fmaf(wv.z, xv.y, acc[2][1]);
            acc[2][2] = fmaf(wv.z, xv.z, acc[2][2]);
            acc[2][3] = fmaf(wv.z, xv.w, acc[2][3]);
            acc[3][0] = fmaf(wv.w, xv.x, acc[3][0]);
            acc[3][1] = fmaf(wv.w, xv.y, acc[3][1]);
            acc[3][2] = fmaf(wv.w, xv.z, acc[3][2]);
            acc[3][3] = fmaf(wv.w, xv.w, acc[3][3]);
        }
        __syncthreads();
    }

    // scatter 16 outputs (global padded c; skip pad c >= 76)
    #pragma unroll
    for (int cc = 0; cc < 4; cc++) {
        int c = zh * 40 + c4 + cc;
        if (c < 76) {
            int kk, cf;
            bool fwd;
            if (c < 38) { kk = kp;     cf = c;      fwd = true;  }
            else        { kk = kp + 3; cf = c - 38; fwd = false; }
            float* base;
            int stride, off;
            if (cf < 6)       { base = g_dtr + (size_t)kk * LTOT * RRK; stride = RRK; off = cf; }
            else if (cf < 22) { base = g_Bm  + (size_t)kk * LTOT * NST; stride = NST; off = cf - 6; }
            else              { base = g_Cm  + (size_t)kk * LTOT * NST; stride = NST; off = cf - 22; }
            #pragma unroll
            for (int ll = 0; ll < 4; ll++) {
                int l = l0 + ls + ll;
                int lw = fwd ? l : (4095 - l);
                base[(size_t)lw * stride + off] = acc[cc][ll];
            }
        }
    }
}

// ---------------- k5: dt_proj + softplus, writes paired (dt, xv) as float2 [l][d] ----------------
__global__ __launch_bounds__(128) void k5_dt(const float* __restrict__ dtw,
                                             const float* __restrict__ dtb) {
    int k = blockIdx.y;
    int l0 = blockIdx.x * 16;
    __shared__ float sw[96 * 6];
    __shared__ float sdt[16 * 6];
    __shared__ float sout[16 * 97];
    __shared__ float sx[16 * 97];
    int t = threadIdx.x;

    for (int i = t; i < 576; i += 128) sw[i] = dtw[k * 576 + i];
    if (t < 96) sdt[t] = g_dtr[((size_t)k * LTOT + l0) * RRK + t];
    {
        int kk = (k < 3) ? k : (k - 3);
        const float* xb = g_xs + (size_t)kk * DCH * LTOT;
        bool rev = (k >= 3);
        for (int j = t; j < 96 * 16; j += 128) {
            int d = j >> 4, li = j & 15;
            int lg = rev ? (4095 - (l0 + li)) : (l0 + li);
            sx[li * 97 + d] = xb[(size_t)d * LTOT + lg];
        }
    }
    __syncthreads();

    if (t < 96) {
        float b = dtb[k * 96 + t];
        float acc[16];
        #pragma unroll
        for (int i = 0; i < 16; i++) acc[i] = b;
        #pragma unroll
        for (int r = 0; r < 6; r++) {
            float wv = sw[t * 6 + r];
            #pragma unroll
            for (int i = 0; i < 16; i++) acc[i] = fmaf(wv, sdt[i * 6 + r], acc[i]);
        }
        #pragma unroll
        for (int i = 0; i < 16; i++) {
            float v = acc[i];
            sout[i * 97 + t] = fmaxf(v, 0.0f) + log1pf(__expf(-fabsf(v)));  // softplus
        }
    }
    __syncthreads();

    float2* dp = g_dx + ((size_t)k * LTOT + l0) * DCH;
    for (int j = t; j < 96 * 16; j += 128) {
        int li = j / 96, d = j % 96;
        dp[li * DCH + d] = make_float2(sout[li * 97 + d], sx[li * 97 + d]);
    }
}

// ---------------- k6 v6: 64-chunk 2-pass scan, 1024 thr (8 warps/SMSP), scalar ex2 ----------------
// block = 1024: ngroup(4) x dgroup(4) x chunk(64 x 64l). grid (24, 6) = 144 blocks.
__global__ __launch_bounds__(1024) void k6_scan(const float* __restrict__ D_skip) {
    int k = blockIdx.y;
    int t = threadIdx.x;
    int g = t & 3;                 // n-group: states 4g..4g+3
    int dl = (t >> 2) & 3;
    int d = blockIdx.x * 4 + dl;
    int chunk = t >> 4;            // 0..63
    int lbase = chunk * 64;

    float A2[4];
    #pragma unroll
    for (int j = 0; j < 4; j++)
        A2[j] = g_A2[((size_t)k * DCH + d) * NST + 4 * g + j];

    const float2* dx0 = g_dx + ((size_t)k * LTOT + lbase) * DCH + d;
    const float4* B0  = (const float4*)(g_Bm + ((size_t)k * LTOT + lbase) * NST) + g;
    const float4* C0  = (const float4*)(g_Cm + ((size_t)k * LTOT + lbase) * NST) + g;

    // pass 1: per-chunk (a, b) per state; a_j = exp2(A2_j * sum(dt))
    float sdt = 0.f;
    float b0 = 0.f, b1 = 0.f, b2 = 0.f, b3 = 0.f;
    {
        const float2* p  = dx0;
        const float4* pb = B0;
        #pragma unroll 4
        for (int i = 0; i < 64; i++) {
            float2 dx = *p;  p += DCH;
            float4 Bv = *pb; pb += 4;
            float dtx = dx.x * dx.y;
            float e0 = ex2_fast(dx.x * A2[0]);
            float e1 = ex2_fast(dx.x * A2[1]);
            float e2 = ex2_fast(dx.x * A2[2]);
            float e3 = ex2_fast(dx.x * A2[3]);
            b0 = fmaf(e0, b0, dtx * Bv.x);
            b1 = fmaf(e1, b1, dtx * Bv.y);
            b2 = fmaf(e2, b2, dtx * Bv.z);
            b3 = fmaf(e3, b3, dtx * Bv.w);
            sdt += dx.x;
        }
    }
    float a0 = ex2_fast(A2[0] * sdt);
    float a1 = ex2_fast(A2[1] * sdt);
    float a2 = ex2_fast(A2[2] * sdt);
    float a3 = ex2_fast(A2[3] * sdt);

    __shared__ float s_a[64][64], s_b[64][64], s_h0[64][64];
    int st = dl * 16 + 4 * g;      // state slot base within block (64 states)
    s_a[chunk][st + 0] = a0;  s_b[chunk][st + 0] = b0;
    s_a[chunk][st + 1] = a1;  s_b[chunk][st + 1] = b1;
    s_a[chunk][st + 2] = a2;  s_b[chunk][st + 2] = b2;
    s_a[chunk][st + 3] = a3;  s_b[chunk][st + 3] = b3;
    __syncthreads();
    if (t < 64) {
        float h = 0.0f;
        #pragma unroll
        for (int ch = 0; ch < 64; ch++) {
            s_h0[ch][t] = h;
            h = fmaf(s_a[ch][t], h, s_b[ch][t]);
        }
    }
    __syncthreads();

    // pass 2: re-scan from chunk prefix, fused y = sum_n h*C + Dskip*xv
    float h0 = s_h0[chunk][st + 0];
    float h1 = s_h0[chunk][st + 1];
    float h2 = s_h0[chunk][st + 2];
    float h3 = s_h0[chunk][st + 3];
    const float Dsk = D_skip[k * 96 + d];
    {
        const float2* p  = dx0;
        const float4* pb = B0;
        const float4* pc = C0;
        float* py = g_ys + ((size_t)k * LTOT + lbase) * DCH + d;
        #pragma unroll 4
        for (int i = 0; i < 64; i++) {
            float2 dx = *p;  p += DCH;
            float4 Bv = *pb; pb += 4;
            float4 Cv = *pc; pc += 4;
            float dtx = dx.x * dx.y;
            float e0 = ex2_fast(dx.x * A2[0]);
            float e1 = ex2_fast(dx.x * A2[1]);
            float e2 = ex2_fast(dx.x * A2[2]);
            float e3 = ex2_fast(dx.x * A2[3]);
            h0 = fmaf(e0, h0, dtx * Bv.x);
            h1 = fmaf(e1, h1, dtx * Bv.y);
            h2 = fmaf(e2, h2, dtx * Bv.z);
            h3 = fmaf(e3, h3, dtx * Bv.w);
            float pacc = h0 * Cv.x;
            pacc = fmaf(h1, Cv.y, pacc);
            pacc = fmaf(h2, Cv.z, pacc);
            pacc = fmaf(h3, Cv.w, pacc);
            pacc += __shfl_xor_sync(0xFFFFFFFFu, pacc, 1);
            pacc += __shfl_xor_sync(0xFFFFFFFFu, pacc, 2);
            if (g == 0) *py = fmaf(Dsk, dx.y, pacc);
            py += DCH;
        }
    }
}

// ---------------- k7: gather 6 directions + LayerNorm(d) + silu(z) gate + out_proj + residual ----------------
__global__ __launch_bounds__(192) void k7_out(const float* __restrict__ x,
                                              const float* __restrict__ onw,
                                              const float* __restrict__ onb,
                                              float* __restrict__ out) {
    __shared__ float sy[16][96];
    __shared__ float sv[16][96];
    int s0 = blockIdx.x * 16;
    int t = threadIdx.x;

    for (int i = t; i < 16 * 96; i += 192) {
        int r = i / 96, d = i % 96;
        int s = s0 + r;
        int dz = s >> 8, hy = (s >> 4) & 15, wx = s & 15;
        int lA = s;
        int lB = (hy << 8) | (wx << 4) | dz;
        int lC = (wx << 8) | (dz << 4) | hy;
        float v = g_ys[((size_t)0 * LTOT + lA) * DCH + d]
                + g_ys[((size_t)1 * LTOT + lB) * DCH + d]
                + g_ys[((size_t)2 * LTOT + lC) * DCH + d]
                + g_ys[((size_t)3 * LTOT + (4095 - lA)) * DCH + d]
                + g_ys[((size_t)4 * LTOT + (4095 - lB)) * DCH + d]
                + g_ys[((size_t)5 * LTOT + (4095 - lC)) * DCH + d];
        sy[r][d] = v;
    }
    __syncthreads();

    int w = t >> 5, lane = t & 31;
    for (int r = w; r < 16; r += 6) {
        float v0 = sy[r][lane], v1 = sy[r][lane + 32], v2 = sy[r][lane + 64];
        float s = v0 + v1 + v2;
        float sq = v0 * v0 + v1 * v1 + v2 * v2;
        #pragma unroll
        for (int o = 16; o; o >>= 1) {
            s += __shfl_xor_sync(0xFFFFFFFFu, s, o);
            sq += __shfl_xor_sync(0xFFFFFFFFu, sq, o);
        }
        float m = s * (1.0f / 96.0f);
        float var = fmaf(-m, m, sq * (1.0f / 96.0f));
        float inv = rsqrtf(var + 1e-5f);
        const float* zr = g_z + (size_t)(s0 + r) * CCH;
        #pragma unroll
        for (int q = 0; q < 3; q++) {
            int c = lane + q * 32;
            float v = (q == 0) ? v0 : ((q == 1) ? v1 : v2);
            float yn = fmaf((v - m) * inv, onw[c], onb[c]);
            float zv = zr[c];
            sv[r][c] = yn * (zv / (1.0f + __expf(-zv)));
        }
    }
    __syncthreads();

    int c = (t < 96) ? t : (t - 96);
    int rbase = (t < 96) ? 0 : 8;
    float acc[8];
    #pragma unroll
    for (int r = 0; r < 8; r++) acc[r] = 0.0f;
    for (int j = 0; j < 96; j += 4) {
        float w0 = g_wot[(j + 0) * 96 + c];
        float w1 = g_wot[(j + 1) * 96 + c];
        float w2 = g_wot[(j + 2) * 96 + c];
        float w3 = g_wot[(j + 3) * 96 + c];
        #pragma unroll
        for (int r = 0; r < 8; r++) {
            float4 yv = *(const float4*)&sv[rbase + r][j];
            acc[r] = fmaf(w0, yv.x, fmaf(w1, yv.y, fmaf(w2, yv.z, fmaf(w3, yv.w, acc[r]))));
        }
    }
    #pragma unroll
    for (int r = 0; r < 8; r++) {
        int s = s0 + rbase + r;
        out[(size_t)s * CCH + c] = x[(size_t)s * CCH + c] + acc[r];
    }
}

// ---------------- launch ----------------
extern "C" void kernel_launch(void* const* d_in, const int* in_sizes, int n_in,
                              void* d_out, int out_size) {
    const float* x         = (const float*)d_in[0];
    const float* ln1_w     = (const float*)d_in[1];
    const float* ln1_b     = (const float*)d_in[2];
    const float* in_proj_w = (const float*)d_in[3];
    const float* conv_w    = (const float*)d_in[4];
    const float* conv_b    = (const float*)d_in[5];
    const float* x_proj_w  = (const float*)d_in[6];
    const float* dt_proj_w = (const float*)d_in[7];
    const float* dt_proj_b = (const float*)d_in[8];
    const float* A_log     = (const float*)d_in[9];
    const float* D_skip    = (const float*)d_in[10];
    const float* out_nw    = (const float*)d_in[11];
    const float* out_nb    = (const float*)d_in[12];
    const float* out_pw    = (const float*)d_in[13];
    float* out = (float*)d_out;

    k0_prep<<<96, 256>>>(in_proj_w, x_proj_w, A_log, out_pw);
    k1_ln_inproj<<<256, 192>>>(x, ln1_w, ln1_b);
    k2_conv<<<96, 256>>>(conv_w, conv_b);
    k4_xdbl<<<dim3(64, 3, 2), 160>>>();
    k5_dt<<<dim3(256, 6), 128>>>(dt_proj_w, dt_proj_b);
    k6_scan<<<dim3(24, 6), 1024>>>(D_skip);
    k7_out<<<256, 192>>>(x, out_nw, out_nb, out);
}